// round 2
// baseline (speedup 1.0000x reference)
#include <cuda_runtime.h>
#include <cstdint>

#define B_  16
#define N_  1024
#define C_  768
#define H_  12
#define D_  64
#define SCALE 0.125f           // hd^-0.5 = 64^-0.5
#define EPSV 1e-6f

// ---------------- scratch (static device globals; no runtime alloc) --------
__device__ float g_q[B_*H_*N_*D_];     // [B,H,N,D]
__device__ float g_k[B_*H_*N_*D_];
__device__ float g_v[B_*H_*N_*D_];
__device__ float g_vsum[B_*H_*D_];     // column sums of V per (b,h)
__device__ float g_att[B_*N_*C_];      // attention output, [B,N,C]

// ---------------------------------------------------------------------------
// Tiled NT GEMM: C[M,Nn] = A[M,K] (row-major) * Bm[Nn,K]^T (row-major).
// BM=128, BN=64, BK=32, 256 threads, 8x4 register tile per thread.
// EPI==0: scatter into g_q/g_k/g_v per the qkv reshape.
// EPI==1: A is g_att, add bias, write Cout.
// ---------------------------------------------------------------------------
template<int EPI>
__global__ __launch_bounds__(256)
void gemm_nt(const float* __restrict__ A, const float* __restrict__ Bm,
             const float* __restrict__ bias, float* __restrict__ Cout,
             int M, int Nn, int K)
{
    __shared__ float As[32][129];   // [k][m], pad 129 -> conflict-free
    __shared__ float Bs[32][65];    // [k][n], pad 65

    const float* Ap = (EPI == 1) ? g_att : A;

    int tid = threadIdx.x;
    int tx  = tid & 15;          // 16 col-groups
    int ty  = tid >> 4;          // 16 row-groups
    int row0 = blockIdx.y * 128;
    int col0 = blockIdx.x * 64;

    float acc[8][4];
    #pragma unroll
    for (int i = 0; i < 8; i++)
        #pragma unroll
        for (int j = 0; j < 4; j++) acc[i][j] = 0.f;

    for (int kt = 0; kt < K; kt += 32) {
        // A tile: 128x32 floats = 1024 float4, 4 per thread
        #pragma unroll
        for (int i = 0; i < 4; i++) {
            int l  = tid + i * 256;
            int r  = l >> 3;
            int c4 = (l & 7) * 4;
            float4 va = *reinterpret_cast<const float4*>(
                &Ap[(size_t)(row0 + r) * K + kt + c4]);
            As[c4 + 0][r] = va.x; As[c4 + 1][r] = va.y;
            As[c4 + 2][r] = va.z; As[c4 + 3][r] = va.w;
        }
        // B tile: 64x32 floats = 512 float4, 2 per thread
        #pragma unroll
        for (int i = 0; i < 2; i++) {
            int l  = tid + i * 256;
            int r  = l >> 3;
            int c4 = (l & 7) * 4;
            float4 vb = *reinterpret_cast<const float4*>(
                &Bm[(size_t)(col0 + r) * K + kt + c4]);
            Bs[c4 + 0][r] = vb.x; Bs[c4 + 1][r] = vb.y;
            Bs[c4 + 2][r] = vb.z; Bs[c4 + 3][r] = vb.w;
        }
        __syncthreads();

        #pragma unroll
        for (int k = 0; k < 32; k++) {
            float a[8], b[4];
            #pragma unroll
            for (int i = 0; i < 8; i++) a[i] = As[k][ty * 8 + i];
            #pragma unroll
            for (int j = 0; j < 4; j++) b[j] = Bs[k][tx + 16 * j];
            #pragma unroll
            for (int i = 0; i < 8; i++)
                #pragma unroll
                for (int j = 0; j < 4; j++)
                    acc[i][j] = fmaf(a[i], b[j], acc[i][j]);
        }
        __syncthreads();
    }

    // epilogue
    #pragma unroll
    for (int i = 0; i < 8; i++) {
        int m = row0 + ty * 8 + i;
        #pragma unroll
        for (int j = 0; j < 4; j++) {
            int jj = col0 + tx + 16 * j;
            float val = acc[i][j];
            if (EPI == 0) {
                // jj -> (which, h, d); m -> (b, n). which is uniform per block.
                int which = jj / 768;
                int rres  = jj % 768;
                int h = rres >> 6, d = rres & 63;
                int b = m >> 10, n = m & 1023;
                size_t off = (((size_t)(b * H_ + h)) * N_ + n) * D_ + d;
                float* dst = (which == 0) ? g_q : ((which == 1) ? g_k : g_v);
                dst[off] = val;
            } else {
                Cout[(size_t)m * Nn + jj] = val + bias[jj];
            }
        }
    }
}

// ---------------------------------------------------------------------------
// Vsum[b,h,d] = sum_n V[b,h,n,d]
// ---------------------------------------------------------------------------
__global__ __launch_bounds__(256)
void vsum_kernel()
{
    int bh  = blockIdx.x;                 // 0..B*H-1
    int tid = threadIdx.x;
    int d = tid & 63, s = tid >> 6;       // 4 slices
    const float* vp = g_v + (size_t)bh * N_ * D_;
    float sum = 0.f;
    for (int n = s; n < N_; n += 4) sum += vp[n * D_ + d];
    __shared__ float red[256];
    red[tid] = sum;
    __syncthreads();
    if (s == 0)
        g_vsum[bh * D_ + d] = red[d] + red[64 + d] + red[128 + d] + red[192 + d];
}

// ---------------------------------------------------------------------------
// Flash attention with policy softmax.
// Block = (q-tile of 128 rows, h, b). 256 threads.
// Thread owns 8 q-rows (rg*8..+7) x 4 columns (cg*4..+3) — columns are
// m-indices during scores, d-indices for the O accumulator.
// ---------------------------------------------------------------------------
#define ATT_SMEM_FLOATS (128*65 + 128*65 + 64*65 + 64*65 + 64)
#define ATT_SMEM_BYTES  (ATT_SMEM_FLOATS * 4)

__global__ __launch_bounds__(256)
void attn_kernel(const float* __restrict__ policy)
{
    extern __shared__ float sm[];
    float* Qs  = sm;                     // [128][65]
    float* Ps  = Qs  + 128 * 65;         // [128][65]
    float* Ks  = Ps  + 128 * 65;         // [64][65]
    float* Vs  = Ks  + 64 * 65;          // [64][65]
    float* pol = Vs  + 64 * 65;          // [64]

    int qt = blockIdx.x, h = blockIdx.y, b = blockIdx.z;
    int tid = threadIdx.x;
    int rg = tid >> 4;                   // 0..15 -> rows rg*8..+7
    int cg = tid & 15;                   // 0..15 -> cols cg*4..+3
    int n0 = qt * 128;

    const float* qp = g_q + ((size_t)(b * H_ + h) * N_ + n0) * D_;
    const float* kp = g_k + (size_t)(b * H_ + h) * N_ * D_;
    const float* vp = g_v + (size_t)(b * H_ + h) * N_ * D_;

    // load Q tile: 128x64 floats = 2048 float4, 8 per thread
    #pragma unroll
    for (int i = 0; i < 8; i++) {
        int l  = tid + i * 256;
        int r  = l >> 4;
        int c4 = (l & 15) * 4;
        float4 v = *reinterpret_cast<const float4*>(&qp[r * D_ + c4]);
        Qs[r * 65 + c4 + 0] = v.x; Qs[r * 65 + c4 + 1] = v.y;
        Qs[r * 65 + c4 + 2] = v.z; Qs[r * 65 + c4 + 3] = v.w;
    }

    float O[8][4];
    float mrun[8], lrun[8];
    #pragma unroll
    for (int i = 0; i < 8; i++) {
        mrun[i] = -1e30f; lrun[i] = 0.f;
        #pragma unroll
        for (int j = 0; j < 4; j++) O[i][j] = 0.f;
    }

    for (int mt = 0; mt < N_ / 64; mt++) {
        __syncthreads();   // previous-iteration readers done before overwrite

        // load K,V tiles: 64x64 floats = 1024 float4 each, 4 per thread
        const float* kt_ = kp + (size_t)mt * 64 * D_;
        const float* vt_ = vp + (size_t)mt * 64 * D_;
        #pragma unroll
        for (int i = 0; i < 4; i++) {
            int l  = tid + i * 256;
            int r  = l >> 4;
            int c4 = (l & 15) * 4;
            float4 kv = *reinterpret_cast<const float4*>(&kt_[r * D_ + c4]);
            Ks[r * 65 + c4 + 0] = kv.x; Ks[r * 65 + c4 + 1] = kv.y;
            Ks[r * 65 + c4 + 2] = kv.z; Ks[r * 65 + c4 + 3] = kv.w;
            float4 vv = *reinterpret_cast<const float4*>(&vt_[r * D_ + c4]);
            Vs[r * 65 + c4 + 0] = vv.x; Vs[r * 65 + c4 + 1] = vv.y;
            Vs[r * 65 + c4 + 2] = vv.z; Vs[r * 65 + c4 + 3] = vv.w;
        }
        if (tid < 64) pol[tid] = policy[(size_t)b * N_ + mt * 64 + tid];
        __syncthreads();

        // scores: S[i][j] = q_{rg*8+i} . k_{cg*4+j}
        float S[8][4];
        #pragma unroll
        for (int i = 0; i < 8; i++)
            #pragma unroll
            for (int j = 0; j < 4; j++) S[i][j] = 0.f;

        for (int d = 0; d < D_; d++) {
            float qv[8], kv[4];
            #pragma unroll
            for (int i = 0; i < 8; i++) qv[i] = Qs[(rg * 8 + i) * 65 + d];
            #pragma unroll
            for (int j = 0; j < 4; j++) kv[j] = Ks[(cg * 4 + j) * 65 + d];
            #pragma unroll
            for (int i = 0; i < 8; i++)
                #pragma unroll
                for (int j = 0; j < 4; j++)
                    S[i][j] = fmaf(qv[i], kv[j], S[i][j]);
        }

        // online softmax update (per row, reduced over the 16 cg lanes)
        #pragma unroll
        for (int i = 0; i < 8; i++) {
            float tmax = -1e30f;
            #pragma unroll
            for (int j = 0; j < 4; j++) {
                S[i][j] *= SCALE;
                tmax = fmaxf(tmax, S[i][j]);
            }
            #pragma unroll
            for (int off = 1; off < 16; off <<= 1)
                tmax = fmaxf(tmax, __shfl_xor_sync(0xffffffffu, tmax, off));

            float mnew  = fmaxf(mrun[i], tmax);
            float alpha = __expf(mrun[i] - mnew);
            mrun[i] = mnew;
            lrun[i] *= alpha;
            #pragma unroll
            for (int j = 0; j < 4; j++) O[i][j] *= alpha;

            int nglob = n0 + rg * 8 + i;
            float psum = 0.f;
            #pragma unroll
            for (int j = 0; j < 4; j++) {
                int mloc  = cg * 4 + j;
                int mglob = mt * 64 + mloc;
                float pfac = (mglob == nglob) ? 1.0f : pol[mloc];
                float p = __expf(S[i][j] - mnew) * pfac;
                Ps[(rg * 8 + i) * 65 + mloc] = p;
                psum += p;
            }
            #pragma unroll
            for (int off = 1; off < 16; off <<= 1)
                psum += __shfl_xor_sync(0xffffffffu, psum, off);
            lrun[i] += psum;
        }
        __syncthreads();

        // O += P @ V  (thread's d-columns: cg*4..+3)
        for (int m = 0; m < 64; m++) {
            float pv[8], vv[4];
            #pragma unroll
            for (int i = 0; i < 8; i++) pv[i] = Ps[(rg * 8 + i) * 65 + m];
            #pragma unroll
            for (int j = 0; j < 4; j++) vv[j] = Vs[m * 65 + cg * 4 + j];
            #pragma unroll
            for (int i = 0; i < 8; i++)
                #pragma unroll
                for (int j = 0; j < 4; j++)
                    O[i][j] = fmaf(pv[i], vv[j], O[i][j]);
        }
    }

    // finalize: (O + (eps/N)*Vsum) / (l + eps); write to [B,N,C]
    const float* vs = g_vsum + (size_t)(b * H_ + h) * D_;
    #pragma unroll
    for (int i = 0; i < 8; i++) {
        int n = n0 + rg * 8 + i;
        float inv = 1.0f / (lrun[i] + EPSV);
        #pragma unroll
        for (int j = 0; j < 4; j++) {
            int d = cg * 4 + j;
            float val = (O[i][j] + (EPSV / (float)N_) * vs[d]) * inv;
            g_att[((size_t)(b * N_ + n)) * C_ + h * D_ + d] = val;
        }
    }
}

// ---------------------------------------------------------------------------
extern "C" void kernel_launch(void* const* d_in, const int* in_sizes, int n_in,
                              void* d_out, int out_size)
{
    const float* x      = (const float*)d_in[0];   // [16,1024,768]
    const float* policy = (const float*)d_in[1];   // [16,1024,1]
    const float* w_qkv  = (const float*)d_in[2];   // [2304,768]
    const float* w_proj = (const float*)d_in[3];   // [768,768]
    const float* b_proj = (const float*)d_in[4];   // [768]
    float* out = (float*)d_out;                    // [16,1024,768]

    // idempotent; executes immediately (not a stream op), capture-safe
    cudaFuncSetAttribute(attn_kernel,
                         cudaFuncAttributeMaxDynamicSharedMemorySize,
                         ATT_SMEM_BYTES);

    const int M = B_ * N_;   // 16384

    // 1) QKV GEMM + scatter into g_q/g_k/g_v
    {
        dim3 grid(3 * C_ / 64, M / 128);
        gemm_nt<0><<<grid, 256>>>(x, w_qkv, nullptr, nullptr, M, 3 * C_, C_);
    }
    // 2) V column sums
    vsum_kernel<<<B_ * H_, 256>>>();
    // 3) flash attention with policy softmax
    {
        dim3 grid(N_ / 128, H_, B_);
        attn_kernel<<<grid, 256, ATT_SMEM_BYTES>>>(policy);
    }
    // 4) output projection + bias
    {
        dim3 grid(C_ / 64, M / 128);
        gemm_nt<1><<<grid, 256>>>(nullptr, w_proj, b_proj, out, M, C_, C_);
    }
}

// round 5
// speedup vs baseline: 1.5172x; 1.5172x over previous
#include <cuda_runtime.h>
#include <cstdint>

#define B_  16
#define N_  1024
#define C_  768
#define H_  12
#define D_  64
#define SCALE 0.125f           // hd^-0.5
#define EPSV 1e-6f

// ---------------- scratch (static device globals; no runtime alloc) --------
__device__ float g_q[B_*H_*N_*D_];     // [B,H,N,D]
__device__ float g_k[B_*H_*N_*D_];
__device__ float g_v[B_*H_*N_*D_];
__device__ float g_vsum[B_*H_*D_];     // column sums of V per (b,h)
__device__ float g_att[B_*N_*C_];      // attention output, [B,N,C]

// ---------------------------------------------------------------------------
__device__ __forceinline__ uint32_t f2tf32(float f) {  // round-to-nearest tf32
    uint32_t r;
    asm("cvt.rna.tf32.f32 %0, %1;" : "=r"(r) : "f"(f));
    return r;
}
__device__ __forceinline__ void mma_tf32(float* d, const uint32_t* a,
                                         const uint32_t* b) {
    asm volatile(
        "mma.sync.aligned.m16n8k8.row.col.f32.tf32.tf32.f32 "
        "{%0,%1,%2,%3}, {%4,%5,%6,%7}, {%8,%9}, {%0,%1,%2,%3};"
        : "+f"(d[0]), "+f"(d[1]), "+f"(d[2]), "+f"(d[3])
        : "r"(a[0]), "r"(a[1]), "r"(a[2]), "r"(a[3]), "r"(b[0]), "r"(b[1]));
}

// ===========================================================================
// mma.sync tf32 NT GEMM: C[M,Nn] = A[M,K] (K-major) * Bm[Nn,K]^T (K-major).
// Block tile 128x128, BK=32, 256 threads (8 warps as 2x4; warp tile 64x32).
// Fragments loaded from SMEM with stride-36 pad => conflict-free LDS.
// EPI==0: scatter into g_q/g_k/g_v per qkv reshape. EPI==1: bias + Cout.
// ===========================================================================
template<int EPI>
__global__ __launch_bounds__(256)
void gemm_mma(const float* __restrict__ A, const float* __restrict__ Bm,
              const float* __restrict__ bias, float* __restrict__ Cout,
              int Nn, int K)
{
    __shared__ float As[128 * 36];
    __shared__ float Bs[128 * 36];

    const float* Ap = (EPI == 1) ? g_att : A;

    const int tid = threadIdx.x;
    const int wid = tid >> 5, lane = tid & 31;
    const int gid = lane >> 2, tig = lane & 3;   // groupID / thread-in-group
    const int m0w = (wid >> 2) * 64;             // warp M offset (0 / 64)
    const int n0w = (wid & 3) * 32;              // warp N offset (0..96)
    const int row0 = blockIdx.y * 128, col0 = blockIdx.x * 128;

    float acc[4][4][4];
    #pragma unroll
    for (int mt = 0; mt < 4; mt++)
        #pragma unroll
        for (int nt = 0; nt < 4; nt++)
            #pragma unroll
            for (int r = 0; r < 4; r++) acc[mt][nt][r] = 0.f;

    // gmem->reg staging: chunk l = tid + i*256 -> row l>>3, col4 (l&7)*4
    float4 av[4], bv[4];
    const int nKt = K / 32;

    // load tile kt into regs
    auto loadT = [&](int kt) {
        #pragma unroll
        for (int i = 0; i < 4; i++) {
            int l = tid + i * 256;
            int r = l >> 3, c = (l & 7) * 4;
            av[i] = *(const float4*)&Ap[(size_t)(row0 + r) * K + kt * 32 + c];
            bv[i] = *(const float4*)&Bm[(size_t)(col0 + r) * K + kt * 32 + c];
        }
    };
    loadT(0);

    for (int kt = 0; kt < nKt; kt++) {
        // regs -> smem with fp32->tf32 rounding
        #pragma unroll
        for (int i = 0; i < 4; i++) {
            int l = tid + i * 256;
            int r = l >> 3, c = (l & 7) * 4;
            uint4 ta, tb;
            ta.x = f2tf32(av[i].x); ta.y = f2tf32(av[i].y);
            ta.z = f2tf32(av[i].z); ta.w = f2tf32(av[i].w);
            tb.x = f2tf32(bv[i].x); tb.y = f2tf32(bv[i].y);
            tb.z = f2tf32(bv[i].z); tb.w = f2tf32(bv[i].w);
            *(uint4*)&As[r * 36 + c] = ta;
            *(uint4*)&Bs[r * 36 + c] = tb;
        }
        __syncthreads();
        if (kt + 1 < nKt) loadT(kt + 1);   // overlap next gmem with compute

        #pragma unroll
        for (int ks = 0; ks < 4; ks++) {
            const int kb = ks * 8;
            uint32_t af[4][4], bf[4][2];
            #pragma unroll
            for (int mt = 0; mt < 4; mt++) {
                const float* ap = &As[(m0w + mt * 16 + gid) * 36 + kb + tig];
                af[mt][0] = __float_as_uint(ap[0]);
                af[mt][1] = __float_as_uint(ap[8 * 36]);
                af[mt][2] = __float_as_uint(ap[4]);
                af[mt][3] = __float_as_uint(ap[8 * 36 + 4]);
            }
            #pragma unroll
            for (int nt = 0; nt < 4; nt++) {
                const float* bp = &Bs[(n0w + nt * 8 + gid) * 36 + kb + tig];
                bf[nt][0] = __float_as_uint(bp[0]);
                bf[nt][1] = __float_as_uint(bp[4]);
            }
            #pragma unroll
            for (int mt = 0; mt < 4; mt++)
                #pragma unroll
                for (int nt = 0; nt < 4; nt++)
                    mma_tf32(acc[mt][nt], af[mt], bf[nt]);
        }
        __syncthreads();
    }

    // ---- epilogue: fragment layout -> gmem (float2 pairs, cols even) ----
    #pragma unroll
    for (int mt = 0; mt < 4; mt++) {
        #pragma unroll
        for (int nt = 0; nt < 4; nt++) {
            #pragma unroll
            for (int half = 0; half < 2; half++) {
                int m  = row0 + m0w + mt * 16 + gid + half * 8;
                int jj = col0 + n0w + nt * 8 + 2 * tig;
                float2 v;
                v.x = acc[mt][nt][half * 2 + 0];
                v.y = acc[mt][nt][half * 2 + 1];
                if (EPI == 1) {
                    v.x += bias[jj]; v.y += bias[jj + 1];
                    *(float2*)&Cout[(size_t)m * Nn + jj] = v;
                } else {
                    int which = jj / 768, res = jj % 768;
                    int h = res >> 6, dd = res & 63;
                    int b = m >> 10, n = m & 1023;
                    float* dst = (which == 0) ? g_q : ((which == 1) ? g_k : g_v);
                    *(float2*)&dst[(((size_t)(b * H_ + h)) * N_ + n) * 64 + dd] = v;
                }
            }
        }
    }
}

// ---------------------------------------------------------------------------
// Vsum[b,h,d] = sum_n V[b,h,n,d]
// ---------------------------------------------------------------------------
__global__ __launch_bounds__(256)
void vsum_kernel()
{
    int bh  = blockIdx.x;
    int tid = threadIdx.x;
    int d = tid & 63, s = tid >> 6;
    const float* vp = g_v + (size_t)bh * N_ * D_;
    float sum = 0.f;
    for (int n = s; n < N_; n += 4) sum += vp[n * D_ + d];
    __shared__ float red[256];
    red[tid] = sum;
    __syncthreads();
    if (s == 0)
        g_vsum[bh * D_ + d] = red[d] + red[64 + d] + red[128 + d] + red[192 + d];
}

// ---------------------------------------------------------------------------
// Flash attention with policy softmax (SIMT fp32, unchanged).
// ---------------------------------------------------------------------------
#define ATT_SMEM_FLOATS (128*65 + 128*65 + 64*65 + 64*65 + 64)
#define ATT_SMEM_BYTES  (ATT_SMEM_FLOATS * 4)

__global__ __launch_bounds__(256)
void attn_kernel(const float* __restrict__ policy)
{
    extern __shared__ float sm[];
    float* Qs  = sm;                     // [128][65]
    float* Ps  = Qs  + 128 * 65;         // [128][65]
    float* Ks  = Ps  + 128 * 65;         // [64][65]
    float* Vs  = Ks  + 64 * 65;          // [64][65]
    float* pol = Vs  + 64 * 65;          // [64]

    int qt = blockIdx.x, h = blockIdx.y, b = blockIdx.z;
    int tid = threadIdx.x;
    int rg = tid >> 4;
    int cg = tid & 15;
    int n0 = qt * 128;

    const float* qp = g_q + ((size_t)(b * H_ + h) * N_ + n0) * D_;
    const float* kp = g_k + (size_t)(b * H_ + h) * N_ * D_;
    const float* vp = g_v + (size_t)(b * H_ + h) * N_ * D_;

    #pragma unroll
    for (int i = 0; i < 8; i++) {
        int l  = tid + i * 256;
        int r  = l >> 4;
        int c4 = (l & 15) * 4;
        float4 v = *reinterpret_cast<const float4*>(&qp[r * D_ + c4]);
        Qs[r * 65 + c4 + 0] = v.x; Qs[r * 65 + c4 + 1] = v.y;
        Qs[r * 65 + c4 + 2] = v.z; Qs[r * 65 + c4 + 3] = v.w;
    }

    float O[8][4];
    float mrun[8], lrun[8];
    #pragma unroll
    for (int i = 0; i < 8; i++) {
        mrun[i] = -1e30f; lrun[i] = 0.f;
        #pragma unroll
        for (int j = 0; j < 4; j++) O[i][j] = 0.f;
    }

    for (int mt = 0; mt < N_ / 64; mt++) {
        __syncthreads();

        const float* kt_ = kp + (size_t)mt * 64 * D_;
        const float* vt_ = vp + (size_t)mt * 64 * D_;
        #pragma unroll
        for (int i = 0; i < 4; i++) {
            int l  = tid + i * 256;
            int r  = l >> 4;
            int c4 = (l & 15) * 4;
            float4 kv = *reinterpret_cast<const float4*>(&kt_[r * D_ + c4]);
            Ks[r * 65 + c4 + 0] = kv.x; Ks[r * 65 + c4 + 1] = kv.y;
            Ks[r * 65 + c4 + 2] = kv.z; Ks[r * 65 + c4 + 3] = kv.w;
            float4 vv = *reinterpret_cast<const float4*>(&vt_[r * D_ + c4]);
            Vs[r * 65 + c4 + 0] = vv.x; Vs[r * 65 + c4 + 1] = vv.y;
            Vs[r * 65 + c4 + 2] = vv.z; Vs[r * 65 + c4 + 3] = vv.w;
        }
        if (tid < 64) pol[tid] = policy[(size_t)b * N_ + mt * 64 + tid];
        __syncthreads();

        float S[8][4];
        #pragma unroll
        for (int i = 0; i < 8; i++)
            #pragma unroll
            for (int j = 0; j < 4; j++) S[i][j] = 0.f;

        for (int d = 0; d < D_; d++) {
            float qv[8], kv[4];
            #pragma unroll
            for (int i = 0; i < 8; i++) qv[i] = Qs[(rg * 8 + i) * 65 + d];
            #pragma unroll
            for (int j = 0; j < 4; j++) kv[j] = Ks[(cg * 4 + j) * 65 + d];
            #pragma unroll
            for (int i = 0; i < 8; i++)
                #pragma unroll
                for (int j = 0; j < 4; j++)
                    S[i][j] = fmaf(qv[i], kv[j], S[i][j]);
        }

        #pragma unroll
        for (int i = 0; i < 8; i++) {
            float tmax = -1e30f;
            #pragma unroll
            for (int j = 0; j < 4; j++) {
                S[i][j] *= SCALE;
                tmax = fmaxf(tmax, S[i][j]);
            }
            #pragma unroll
            for (int off = 1; off < 16; off <<= 1)
                tmax = fmaxf(tmax, __shfl_xor_sync(0xffffffffu, tmax, off));

            float mnew  = fmaxf(mrun[i], tmax);
            float alpha = __expf(mrun[i] - mnew);
            mrun[i] = mnew;
            lrun[i] *= alpha;
            #pragma unroll
            for (int j = 0; j < 4; j++) O[i][j] *= alpha;

            int nglob = n0 + rg * 8 + i;
            float psum = 0.f;
            #pragma unroll
            for (int j = 0; j < 4; j++) {
                int mloc  = cg * 4 + j;
                int mglob = mt * 64 + mloc;
                float pfac = (mglob == nglob) ? 1.0f : pol[mloc];
                float p = __expf(S[i][j] - mnew) * pfac;
                Ps[(rg * 8 + i) * 65 + mloc] = p;
                psum += p;
            }
            #pragma unroll
            for (int off = 1; off < 16; off <<= 1)
                psum += __shfl_xor_sync(0xffffffffu, psum, off);
            lrun[i] += psum;
        }
        __syncthreads();

        for (int m = 0; m < 64; m++) {
            float pv[8], vv[4];
            #pragma unroll
            for (int i = 0; i < 8; i++) pv[i] = Ps[(rg * 8 + i) * 65 + m];
            #pragma unroll
            for (int j = 0; j < 4; j++) vv[j] = Vs[m * 65 + cg * 4 + j];
            #pragma unroll
            for (int i = 0; i < 8; i++)
                #pragma unroll
                for (int j = 0; j < 4; j++)
                    O[i][j] = fmaf(pv[i], vv[j], O[i][j]);
        }
    }

    const float* vs = g_vsum + (size_t)(b * H_ + h) * D_;
    #pragma unroll
    for (int i = 0; i < 8; i++) {
        int n = n0 + rg * 8 + i;
        float inv = 1.0f / (lrun[i] + EPSV);
        #pragma unroll
        for (int j = 0; j < 4; j++) {
            int d = cg * 4 + j;
            float val = (O[i][j] + (EPSV / (float)N_) * vs[d]) * inv;
            g_att[((size_t)(b * N_ + n)) * C_ + h * D_ + d] = val;
        }
    }
}

// ---------------------------------------------------------------------------
extern "C" void kernel_launch(void* const* d_in, const int* in_sizes, int n_in,
                              void* d_out, int out_size)
{
    const float* x      = (const float*)d_in[0];   // [16,1024,768]
    const float* policy = (const float*)d_in[1];   // [16,1024,1]
    const float* w_qkv  = (const float*)d_in[2];   // [2304,768]
    const float* w_proj = (const float*)d_in[3];   // [768,768]
    const float* b_proj = (const float*)d_in[4];   // [768]
    float* out = (float*)d_out;                    // [16,1024,768]

    cudaFuncSetAttribute(attn_kernel,
                         cudaFuncAttributeMaxDynamicSharedMemorySize,
                         ATT_SMEM_BYTES);

    // 1) QKV GEMM (tf32 mma.sync) + scatter into g_q/g_k/g_v
    {
        dim3 grid(3 * C_ / 128, (B_ * N_) / 128);   // (18, 128)
        gemm_mma<0><<<grid, 256>>>(x, w_qkv, nullptr, nullptr, 3 * C_, C_);
    }
    // 2) V column sums
    vsum_kernel<<<B_ * H_, 256>>>();
    // 3) flash attention with policy softmax (SIMT fp32)
    {
        dim3 grid(N_ / 128, H_, B_);
        attn_kernel<<<grid, 256, ATT_SMEM_BYTES>>>(policy);
    }
    // 4) output projection (tf32 mma.sync) + bias
    {
        dim3 grid(C_ / 128, (B_ * N_) / 128);       // (6, 128)
        gemm_mma<1><<<grid, 256>>>(nullptr, w_proj, b_proj, out, C_, C_);
    }
}